// round 11
// baseline (speedup 1.0000x reference)
#include <cuda_runtime.h>

// EMD approx-match (auction annealing), B=8, N=M=2048, 3-D points.
// R10: Morton-sort both clouds once -> spatially coherent warps/columns, so
// (a) existing underflow ballots actually skip, (b) per-256-column-segment
// AABB bound tests skip whole inner loops at the 5 sparse annealing levels.
// Persistent kernel, __noinline__ phases, per-batch reset-free barriers.

#define BB 8
#define NN 2048
#define MM 2048
#define EPSF 1e-9f
#define LOG2E 1.4426950408889634f
#define TMIN -126.0f

#define NT   1024
#define RPC  128
#define SEGS 8
#define SEGL 256

// dynamic shared memory layout
#define SM_TILE    0        // float4[2048] 32768  (sort reuses as u64[2048])
#define SM_TILE2   32768    // float[2048]   8192
#define SM_RED     40960    // float[1024]   4096
#define SM_CWARP   45056    // float[32]      128
#define SM_WMAX1   45184    // float[64]      256
#define SM_WMAX2   45440    // float[64]      256
#define SM_SEGMAX1 45696    // float[8]        32
#define SM_SEGMAX2 45728    // float[8]        32
#define SM_SLS     45760
#define SM_TOTAL   45824

__device__ float4 g_p1[BB * NN], g_p2[BB * MM];       // sorted (x,y,z,|p|^2)
__device__ float4 g_b1lo[BB * SEGS], g_b1hi[BB * SEGS];
__device__ float4 g_b2lo[BB * SEGS], g_b2hi[BB * SEGS];
__device__ float g_s [BB * NN];
__device__ float g_ss[BB * MM];
__device__ float g_rL[2][BB * NN];
__device__ float g_rR[2][BB * MM];
__device__ unsigned g_barb[BB];

__constant__ float c_lv[10] = {
    -16384.f, -4096.f, -1024.f, -256.f, -64.f, -16.f, -4.f, -1.f, -0.25f, 0.f
};

__device__ __forceinline__ float lg2f(float x) {
    float r; asm("lg2.approx.f32 %0, %1;" : "=f"(r) : "f"(x)); return r;
}
__device__ __forceinline__ float ex2f(float x) {
    float r; asm("ex2.approx.f32 %0, %1;" : "=f"(r) : "f"(x)); return r;
}
__device__ __forceinline__ float sqrt_apx(float x) {
    float r; asm("sqrt.approx.f32 %0, %1;" : "=f"(r) : "f"(x)); return r;
}
__device__ __forceinline__ unsigned expand10(unsigned v) {
    v &= 1023u;
    v = (v | (v << 16)) & 0x030000FFu;
    v = (v | (v << 8))  & 0x0300F00Fu;
    v = (v | (v << 4))  & 0x030C30C3u;
    v = (v | (v << 2))  & 0x09249249u;
    return v;
}
__device__ __forceinline__ float boxd2(float x, float y, float z,
                                       float4 lo, float4 hi) {
    float dx = fmaxf(fmaxf(lo.x - x, x - hi.x), 0.f);
    float dy = fmaxf(fmaxf(lo.y - y, y - hi.y), 0.f);
    float dz = fmaxf(fmaxf(lo.z - z, z - hi.z), 0.f);
    return fmaf(dx, dx, fmaf(dy, dy, dz * dz));
}

// Per-batch reset-free barrier (16 CTAs). Counter is monotonic; every kernel
// execution adds a multiple of 16 per counter, so (arr & ~15)+16 is always
// the right release target, across phases and graph replays.
__device__ __forceinline__ void batch_sync(int b) {
    __syncthreads();
    if (threadIdx.x == 0) {
        __threadfence();
        unsigned arr = atomicAdd(&g_barb[b], 1u);
        unsigned target = (arr & ~15u) + 16u;
        unsigned curv;
        do {
            __nanosleep(32);
            asm volatile("ld.global.cv.u32 %0, [%1];" : "=r"(curv) : "l"(&g_barb[b]));
        } while ((int)(curv - target) < 0);
        __threadfence();
    }
    __syncthreads();
}

// ---------------- generic dot-form sum loop (rowsum/colsum) ----------------
template <int TIER>
__device__ __forceinline__ float dot_loop(const float4* __restrict__ tile,
                                          int n0, float X0, float X1, float X2,
                                          float c) {
    float s0 = 0.f, s1 = 0.f, s2 = 0.f, s3 = 0.f;
#pragma unroll 4
    for (int n = n0; n < n0 + SEGL; n += 4) {
        float4 P0 = tile[n + 0], P1 = tile[n + 1], P2 = tile[n + 2], P3 = tile[n + 3];
        float t0 = fmaf(X0, P0.x, fmaf(X1, P0.y, fmaf(X2, P0.z, c + P0.w)));
        float t1 = fmaf(X0, P1.x, fmaf(X1, P1.y, fmaf(X2, P1.z, c + P1.w)));
        float t2 = fmaf(X0, P2.x, fmaf(X1, P2.y, fmaf(X2, P2.z, c + P2.w)));
        float t3 = fmaf(X0, P3.x, fmaf(X1, P3.y, fmaf(X2, P3.z, c + P3.w)));
        bool go = true;
        if (TIER >= 1) {
            float tm = fmaxf(fmaxf(t0, t1), fmaxf(t2, t3));
            go = __ballot_sync(0xffffffffu, tm > TMIN) != 0u;
        }
        if (go) {
            s0 += ex2f(t0); s1 += ex2f(t1); s2 += ex2f(t2); s3 += ex2f(t3);
        }
    }
    return (s0 + s1) + (s2 + s3);
}

// ---------------- phase -1: Morton sort + boxes + init ----------------
__device__ __noinline__ void phase_sort(const float* __restrict__ x1,
                                        const float* __restrict__ x2,
                                        float* __restrict__ out) {
    extern __shared__ char smem[];
    unsigned long long* keys = (unsigned long long*)(smem + SM_TILE);
    const int b = blockIdx.y, bx = blockIdx.x, tid = threadIdx.x;

    if (bx < 2) {
        const float* src = (bx == 0) ? x1 + (size_t)b * NN * 3
                                     : x2 + (size_t)b * MM * 3;
        float4* dst = (bx == 0) ? g_p1 + b * NN : g_p2 + b * MM;

        for (int j = tid; j < NN; j += NT) {
            float x = src[j * 3], y = src[j * 3 + 1], z = src[j * 3 + 2];
            unsigned ux = (unsigned)(int)fminf(fmaxf((x + 5.f) * 102.4f, 0.f), 1023.f);
            unsigned uy = (unsigned)(int)fminf(fmaxf((y + 5.f) * 102.4f, 0.f), 1023.f);
            unsigned uz = (unsigned)(int)fminf(fmaxf((z + 5.f) * 102.4f, 0.f), 1023.f);
            unsigned code = (expand10(ux) << 2) | (expand10(uy) << 1) | expand10(uz);
            keys[j] = ((unsigned long long)code << 11) | (unsigned)j;
        }
        __syncthreads();
        for (int k = 2; k <= NN; k <<= 1) {
            for (int jj = k >> 1; jj > 0; jj >>= 1) {
                for (int i2 = tid; i2 < NN; i2 += NT) {
                    int ixj = i2 ^ jj;
                    if (ixj > i2) {
                        bool up = ((i2 & k) == 0);
                        unsigned long long a = keys[i2], bb = keys[ixj];
                        if ((a > bb) == up) { keys[i2] = bb; keys[ixj] = a; }
                    }
                }
                __syncthreads();
            }
        }
        for (int j = tid; j < NN; j += NT) {
            int idx = (int)(keys[j] & 2047ull);
            float x = src[idx * 3], y = src[idx * 3 + 1], z = src[idx * 3 + 2];
            dst[j] = make_float4(x, y, z, fmaf(x, x, fmaf(y, y, z * z)));
        }
        __syncthreads();
        // per-256-point AABBs
        float4* blo = (bx == 0) ? g_b1lo : g_b2lo;
        float4* bhi = (bx == 0) ? g_b1hi : g_b2hi;
        if (tid < 256) {
            int seg = tid >> 5, ln = tid & 31;
            float lx = 1e30f, ly = 1e30f, lz = 1e30f;
            float hx = -1e30f, hy = -1e30f, hz = -1e30f;
            for (int e = ln; e < SEGL; e += 32) {
                float4 p = dst[seg * SEGL + e];
                lx = fminf(lx, p.x); ly = fminf(ly, p.y); lz = fminf(lz, p.z);
                hx = fmaxf(hx, p.x); hy = fmaxf(hy, p.y); hz = fmaxf(hz, p.z);
            }
#pragma unroll
            for (int off = 16; off; off >>= 1) {
                lx = fminf(lx, __shfl_down_sync(0xffffffffu, lx, off));
                ly = fminf(ly, __shfl_down_sync(0xffffffffu, ly, off));
                lz = fminf(lz, __shfl_down_sync(0xffffffffu, lz, off));
                hx = fmaxf(hx, __shfl_down_sync(0xffffffffu, hx, off));
                hy = fmaxf(hy, __shfl_down_sync(0xffffffffu, hy, off));
                hz = fmaxf(hz, __shfl_down_sync(0xffffffffu, hz, off));
            }
            if (ln == 0) {
                blo[b * SEGS + seg] = make_float4(lx, ly, lz, 0.f);
                bhi[b * SEGS + seg] = make_float4(hx, hy, hz, 0.f);
            }
        }
    } else if (bx == 2) {
        for (int j = tid; j < NN; j += NT) g_rL[0][b * NN + j] = 1.0f;
    } else if (bx == 3) {
        for (int j = tid; j < MM; j += NT) g_rR[0][b * MM + j] = 1.0f;
    } else if (bx == 4 && tid == 0) {
        out[b] = 0.0f;
    }
}

// ---------------- phase 0: rowsum(level 0), rR==1 ----------------
__device__ __noinline__ void phase0() {
    extern __shared__ char smem[];
    float4* tile = (float4*)(smem + SM_TILE);
    float*  red  = (float*)(smem + SM_RED);
    const int b = blockIdx.y, bx = blockIdx.x, tid = threadIdx.x;
    const int r = bx * RPC + (tid & (RPC - 1));
    const int m0 = (tid >> 7) * SEGL, seg = tid >> 7;
    const float q = c_lv[0] * LOG2E;
    const float n2q = -2.0f * q;

    for (int j = tid; j < MM; j += NT) {
        float4 p = g_p2[b * MM + j];
        tile[j] = make_float4(n2q * p.x, n2q * p.y, n2q * p.z, q * p.w);
    }
    __syncthreads();
    float4 X = g_p1[b * NN + r];
    float a = q * X.w;
    float dlb = boxd2(X.x, X.y, X.z, g_b2lo[b * SEGS + seg], g_b2hi[b * SEGS + seg]);
    float sres = 0.f;
    if (__ballot_sync(0xffffffffu, dlb * q > TMIN) != 0u)
        sres = dot_loop<2>(tile, m0, X.x, X.y, X.z, a);
    red[tid] = sres;
    __syncthreads();
    if (tid < RPC) {
        float v = 0.f;
#pragma unroll
        for (int k = 0; k < SEGS; k++) v += red[tid + (k << 7)];
        g_s[b * NN + bx * RPC + tid] = v;
    }
}

// ---------------- colsum: ss[b][m] ----------------
template <int T>
__device__ __noinline__ void phase_colsum(int cur, float q) {
    extern __shared__ char smem[];
    float4* tile  = (float4*)(smem + SM_TILE);
    float*  red   = (float*)(smem + SM_RED);
    float*  wmax1 = (float*)(smem + SM_WMAX1);
    float*  sgm1  = (float*)(smem + SM_SEGMAX1);
    const int b = blockIdx.y, bx = blockIdx.x, tid = threadIdx.x;
    const int mcol = bx * RPC + (tid & (RPC - 1));
    const int n0 = (tid >> 7) * SEGL, seg = tid >> 7;
    const float n2q = -2.0f * q;

    for (int j = tid; j < NN; j += NT) {
        float4 p = g_p1[b * NN + j];
        float rl = g_rL[cur][b * NN + j];
        float sv = g_s[b * NN + j];
        float lr = lg2f(__fdividef(rl, sv + EPSF));
        tile[j] = make_float4(n2q * p.x, n2q * p.y, n2q * p.z, fmaf(q, p.w, lr));
        if (T == 2) {
            float m = lr;
#pragma unroll
            for (int off = 16; off; off >>= 1)
                m = fmaxf(m, __shfl_xor_sync(0xffffffffu, m, off));
            if ((tid & 31) == 0) wmax1[j >> 5] = m;
        }
    }
    if (T == 2) {
        __syncthreads();
        if (tid < SEGS) {
            float v = -1e30f;
#pragma unroll
            for (int k = 0; k < 8; k++) v = fmaxf(v, wmax1[tid * 8 + k]);
            sgm1[tid] = v;
        }
    }
    __syncthreads();

    float4 Y = g_p2[b * MM + mcol];
    float lrm = lg2f(g_rR[cur][b * MM + mcol]);
    float c = fmaf(q, Y.w, lrm);
    float res = 0.f;
    bool alive = true;
    if (T == 2) {
        float dlb = boxd2(Y.x, Y.y, Y.z, g_b1lo[b * SEGS + seg], g_b1hi[b * SEGS + seg]);
        alive = __ballot_sync(0xffffffffu, fmaf(dlb, q, sgm1[seg] + lrm) > TMIN) != 0u;
    }
    if (alive) res = dot_loop<T>(tile, n0, Y.x, Y.y, Y.z, c);
    red[tid] = res;
    __syncthreads();
    if (tid < RPC) {
        float v = 0.f;
#pragma unroll
        for (int k = 0; k < SEGS; k++) v += red[tid + (k << 7)];
        g_ss[b * MM + bx * RPC + tid] = v;
    }
}

// ---------------- fused: pass3(level i) + rowsum(level i+1) ----------------
template <int T1, int T2>
__device__ __noinline__ void phase_fused(int cur, float q, float q2,
                                         float* __restrict__ out) {
    extern __shared__ char smem[];
    float4* tile  = (float4*)(smem + SM_TILE);
    float*  tile2 = (float*)(smem + SM_TILE2);
    float*  red   = (float*)(smem + SM_RED);
    float*  cwarp = (float*)(smem + SM_CWARP);
    float*  wmax1 = (float*)(smem + SM_WMAX1);
    float*  wmax2 = (float*)(smem + SM_WMAX2);
    float*  sgm1  = (float*)(smem + SM_SEGMAX1);
    float*  sgm2  = (float*)(smem + SM_SEGMAX2);
    const int b = blockIdx.y, bx = blockIdx.x, tid = threadIdx.x;
    const int lane = tid & 31, wid = tid >> 5;
    const int r  = bx * RPC + (tid & (RPC - 1));
    const int m0 = (tid >> 7) * SEGL, seg = tid >> 7;
    const int rown = b * NN + bx * RPC + tid;

    for (int j = tid; j < MM; j += NT) {
        float4 p = g_p2[b * MM + j];
        float rr  = g_rR[cur][b * MM + j];
        float ssv = g_ss[b * MM + j];
        float ratio = fminf(__fdividef(rr, ssv + EPSF), 1.0f);
        float lr1 = lg2f(rr * ratio);
        tile[j] = make_float4(p.x, p.y, p.z, lr1);
        float rrn = fmaxf(rr - ratio * ssv, 0.0f);
        float lr2 = lg2f(rrn);
        tile2[j] = lr2;
        if (bx == 0) g_rR[cur ^ 1][b * MM + j] = rrn;   // exact identity
        if (T1 == 2) {
            float m = lr1;
#pragma unroll
            for (int off = 16; off; off >>= 1)
                m = fmaxf(m, __shfl_xor_sync(0xffffffffu, m, off));
            if ((tid & 31) == 0) wmax1[j >> 5] = m;
        }
        if (T2 == 2) {
            float m = lr2;
#pragma unroll
            for (int off = 16; off; off >>= 1)
                m = fmaxf(m, __shfl_xor_sync(0xffffffffu, m, off));
            if ((tid & 31) == 0) wmax2[j >> 5] = m;
        }
    }
    if (T1 == 2 || T2 == 2) {
        __syncthreads();
        if (tid < SEGS) {
            if (T1 == 2) {
                float v = -1e30f;
#pragma unroll
                for (int k = 0; k < 8; k++) v = fmaxf(v, wmax1[tid * 8 + k]);
                sgm1[tid] = v;
            }
            if (T2 == 2) {
                float v = -1e30f;
#pragma unroll
                for (int k = 0; k < 8; k++) v = fmaxf(v, wmax2[tid * 8 + k]);
                sgm2[tid] = v;
            }
        }
    }
    __syncthreads();

    float4 X = g_p1[b * NN + r];
    float rl = g_rL[cur][b * NN + r];
    float sv = g_s[b * NN + r];
    float F  = __fdividef(rl, sv + EPSF);

    bool aliveT = true, aliveU = true;
    if (T1 == 2 || T2 == 2) {
        float dlb = boxd2(X.x, X.y, X.z, g_b2lo[b * SEGS + seg], g_b2hi[b * SEGS + seg]);
        if (T1 == 2)
            aliveT = __ballot_sync(0xffffffffu, fmaf(dlb, q, sgm1[seg]) > TMIN) != 0u;
        if (T2 == 2)
            aliveU = __ballot_sync(0xffffffffu, fmaf(dlb, q2, sgm2[seg]) > TMIN) != 0u;
    }

    float rs = 0.f, cc = 0.f, sn = 0.f;
    const float4* t2v = (const float4*)tile2;
    if (aliveT && aliveU) {
        float rs0 = 0.f, rs1 = 0.f, c0 = 0.f, c1 = 0.f, sn0 = 0.f, sn1 = 0.f;
        for (int m = m0; m < m0 + SEGL; m += 4) {
            float4 P0 = tile[m + 0], P1 = tile[m + 1], P2 = tile[m + 2], P3 = tile[m + 3];
            float4 T  = t2v[m >> 2];
            float dx0 = X.x - P0.x, dy0 = X.y - P0.y, dz0 = X.z - P0.z;
            float dx1 = X.x - P1.x, dy1 = X.y - P1.y, dz1 = X.z - P1.z;
            float dx2 = X.x - P2.x, dy2 = X.y - P2.y, dz2 = X.z - P2.z;
            float dx3 = X.x - P3.x, dy3 = X.y - P3.y, dz3 = X.z - P3.z;
            float d20 = fmaf(dx0, dx0, fmaf(dy0, dy0, dz0 * dz0));
            float d21 = fmaf(dx1, dx1, fmaf(dy1, dy1, dz1 * dz1));
            float d22 = fmaf(dx2, dx2, fmaf(dy2, dy2, dz2 * dz2));
            float d23 = fmaf(dx3, dx3, fmaf(dy3, dy3, dz3 * dz3));
            float t0 = fmaf(d20, q, P0.w);
            float t1 = fmaf(d21, q, P1.w);
            float t2 = fmaf(d22, q, P2.w);
            float t3 = fmaf(d23, q, P3.w);
            bool go1 = true;
            if (T1 >= 1) {
                float tm = fmaxf(fmaxf(t0, t1), fmaxf(t2, t3));
                go1 = __ballot_sync(0xffffffffu, tm > TMIN) != 0u;
            }
            if (go1) {
                float w0 = ex2f(t0), w1 = ex2f(t1), w2 = ex2f(t2), w3 = ex2f(t3);
                rs0 += w0 + w2; rs1 += w1 + w3;
                c0 = fmaf(w0, sqrt_apx(d20), c0);
                c1 = fmaf(w1, sqrt_apx(d21), c1);
                c0 = fmaf(w2, sqrt_apx(d22), c0);
                c1 = fmaf(w3, sqrt_apx(d23), c1);
            }
            float u0 = fmaf(d20, q2, T.x);
            float u1 = fmaf(d21, q2, T.y);
            float u2 = fmaf(d22, q2, T.z);
            float u3 = fmaf(d23, q2, T.w);
            bool go2 = true;
            if (T2 >= 1) {
                float um = fmaxf(fmaxf(u0, u1), fmaxf(u2, u3));
                go2 = __ballot_sync(0xffffffffu, um > TMIN) != 0u;
            }
            if (go2) {
                sn0 += ex2f(u0) + ex2f(u2);
                sn1 += ex2f(u1) + ex2f(u3);
            }
        }
        rs = rs0 + rs1; cc = c0 + c1; sn = sn0 + sn1;
    } else if (aliveT) {
        float rs0 = 0.f, rs1 = 0.f, c0 = 0.f, c1 = 0.f;
        for (int m = m0; m < m0 + SEGL; m += 4) {
            float4 P0 = tile[m + 0], P1 = tile[m + 1], P2 = tile[m + 2], P3 = tile[m + 3];
            float dx0 = X.x - P0.x, dy0 = X.y - P0.y, dz0 = X.z - P0.z;
            float dx1 = X.x - P1.x, dy1 = X.y - P1.y, dz1 = X.z - P1.z;
            float dx2 = X.x - P2.x, dy2 = X.y - P2.y, dz2 = X.z - P2.z;
            float dx3 = X.x - P3.x, dy3 = X.y - P3.y, dz3 = X.z - P3.z;
            float d20 = fmaf(dx0, dx0, fmaf(dy0, dy0, dz0 * dz0));
            float d21 = fmaf(dx1, dx1, fmaf(dy1, dy1, dz1 * dz1));
            float d22 = fmaf(dx2, dx2, fmaf(dy2, dy2, dz2 * dz2));
            float d23 = fmaf(dx3, dx3, fmaf(dy3, dy3, dz3 * dz3));
            float t0 = fmaf(d20, q, P0.w);
            float t1 = fmaf(d21, q, P1.w);
            float t2 = fmaf(d22, q, P2.w);
            float t3 = fmaf(d23, q, P3.w);
            bool go1 = true;
            if (T1 >= 1) {
                float tm = fmaxf(fmaxf(t0, t1), fmaxf(t2, t3));
                go1 = __ballot_sync(0xffffffffu, tm > TMIN) != 0u;
            }
            if (go1) {
                float w0 = ex2f(t0), w1 = ex2f(t1), w2 = ex2f(t2), w3 = ex2f(t3);
                rs0 += w0 + w2; rs1 += w1 + w3;
                c0 = fmaf(w0, sqrt_apx(d20), c0);
                c1 = fmaf(w1, sqrt_apx(d21), c1);
                c0 = fmaf(w2, sqrt_apx(d22), c0);
                c1 = fmaf(w3, sqrt_apx(d23), c1);
            }
        }
        rs = rs0 + rs1; cc = c0 + c1;
    } else if (aliveU) {
        float sn0 = 0.f, sn1 = 0.f;
        for (int m = m0; m < m0 + SEGL; m += 4) {
            float4 P0 = tile[m + 0], P1 = tile[m + 1], P2 = tile[m + 2], P3 = tile[m + 3];
            float4 T  = t2v[m >> 2];
            float dx0 = X.x - P0.x, dy0 = X.y - P0.y, dz0 = X.z - P0.z;
            float dx1 = X.x - P1.x, dy1 = X.y - P1.y, dz1 = X.z - P1.z;
            float dx2 = X.x - P2.x, dy2 = X.y - P2.y, dz2 = X.z - P2.z;
            float dx3 = X.x - P3.x, dy3 = X.y - P3.y, dz3 = X.z - P3.z;
            float d20 = fmaf(dx0, dx0, fmaf(dy0, dy0, dz0 * dz0));
            float d21 = fmaf(dx1, dx1, fmaf(dy1, dy1, dz1 * dz1));
            float d22 = fmaf(dx2, dx2, fmaf(dy2, dy2, dz2 * dz2));
            float d23 = fmaf(dx3, dx3, fmaf(dy3, dy3, dz3 * dz3));
            float u0 = fmaf(d20, q2, T.x);
            float u1 = fmaf(d21, q2, T.y);
            float u2 = fmaf(d22, q2, T.z);
            float u3 = fmaf(d23, q2, T.w);
            bool go2 = true;
            if (T2 >= 1) {
                float um = fmaxf(fmaxf(u0, u1), fmaxf(u2, u3));
                go2 = __ballot_sync(0xffffffffu, um > TMIN) != 0u;
            }
            if (go2) {
                sn0 += ex2f(u0) + ex2f(u2);
                sn1 += ex2f(u1) + ex2f(u3);
            }
        }
        sn = sn0 + sn1;
    }

    float c = cc * F;
#pragma unroll
    for (int off = 16; off > 0; off >>= 1)
        c += __shfl_down_sync(0xffffffffu, c, off);
    if (lane == 0) cwarp[wid] = c;

    red[tid] = rs;
    __syncthreads();
    if (tid < RPC) {
        float v = 0.f;
#pragma unroll
        for (int k = 0; k < SEGS; k++) v += red[tid + (k << 7)];
        g_rL[cur ^ 1][rown] = fmaxf(rl - v * F, 0.0f);   // tid<RPC owns row r
    }
    __syncthreads();
    red[tid] = sn;
    __syncthreads();
    if (tid < RPC) {
        float v = 0.f;
#pragma unroll
        for (int k = 0; k < SEGS; k++) v += red[tid + (k << 7)];
        g_s[rown] = v;                                   // rowsum level i+1
    }
    if (wid == 0) {
        float v = cwarp[lane];
#pragma unroll
        for (int off = 16; off > 0; off >>= 1)
            v += __shfl_down_sync(0xffffffffu, v, off);
        if (lane == 0) atomicAdd(&out[b], v);
    }
}

// ---------------- level 9 (L=0): analytic s/ss, one cost pass ----------------
__device__ __noinline__ void phase_last(int cur, float* __restrict__ out) {
    extern __shared__ char smem[];
    float4* tile  = (float4*)(smem + SM_TILE);
    float*  red   = (float*)(smem + SM_RED);
    float*  cwarp = (float*)(smem + SM_CWARP);
    float*  SLs   = (float*)(smem + SM_SLS);
    const int b = blockIdx.y, bx = blockIdx.x, tid = threadIdx.x;
    const int lane = tid & 31, wid = tid >> 5;
    const int r  = bx * RPC + (tid & (RPC - 1));
    const int m0 = (tid >> 7) * SEGL;

    const float* rR = g_rR[cur] + b * MM;
    const float* rL = g_rL[cur] + b * NN;
    const float* sp = g_s + b * NN;   // s[n] = sum rR (from fused(8), q2=0)

    float acc = 0.f;
    for (int j = tid; j < NN; j += NT)
        acc += __fdividef(rL[j], sp[j] + EPSF);
    red[tid] = acc;
    __syncthreads();
    if (tid < 32) {
        float v = 0.f;
#pragma unroll
        for (int k = 0; k < NT / 32; k++) v += red[tid + k * 32];
#pragma unroll
        for (int off = 16; off > 0; off >>= 1)
            v += __shfl_down_sync(0xffffffffu, v, off);
        if (tid == 0) *SLs = v;
    }
    __syncthreads();
    const float SL = *SLs;

    for (int j = tid; j < MM; j += NT) {
        float4 p = g_p2[b * MM + j];
        float rr = rR[j];
        float ratio = fminf(__fdividef(rr, fmaf(rr, SL, EPSF)), 1.0f);
        tile[j] = make_float4(p.x, p.y, p.z, rr * ratio);
    }
    __syncthreads();

    float4 X = g_p1[b * NN + r];
    float F = __fdividef(rL[r], sp[r] + EPSF);
    float c0 = 0.f, c1 = 0.f;
#pragma unroll 2
    for (int m = m0; m < m0 + SEGL; m += 2) {
        float4 P0 = tile[m + 0], P1 = tile[m + 1];
        float dx0 = X.x - P0.x, dy0 = X.y - P0.y, dz0 = X.z - P0.z;
        float dx1 = X.x - P1.x, dy1 = X.y - P1.y, dz1 = X.z - P1.z;
        float d20 = fmaf(dx0, dx0, fmaf(dy0, dy0, dz0 * dz0));
        float d21 = fmaf(dx1, dx1, fmaf(dy1, dy1, dz1 * dz1));
        c0 = fmaf(P0.w, sqrt_apx(d20), c0);
        c1 = fmaf(P1.w, sqrt_apx(d21), c1);
    }
    float c = (c0 + c1) * F;
#pragma unroll
    for (int off = 16; off > 0; off >>= 1)
        c += __shfl_down_sync(0xffffffffu, c, off);
    if (lane == 0) cwarp[wid] = c;
    __syncthreads();
    if (wid == 0) {
        float v = cwarp[lane];
#pragma unroll
        for (int off = 16; off > 0; off >>= 1)
            v += __shfl_down_sync(0xffffffffu, v, off);
        if (lane == 0) atomicAdd(&out[b], v);
    }
}

__global__ void __launch_bounds__(NT, 1)
k_emd(const float* __restrict__ x1, const float* __restrict__ x2,
      float* __restrict__ out) {
    const int b = blockIdx.y;

    phase_sort(x1, x2, out);
    batch_sync(b);

    phase0();
    batch_sync(b);

    int cur = 0;
#pragma unroll 1
    for (int i = 0; i < 9; i++) {
        const float q  = c_lv[i] * LOG2E;
        const float q2 = c_lv[i + 1] * LOG2E;

        if (i <= 3) {
            phase_colsum<2>(cur, q);  batch_sync(b);
            phase_fused<2, 2>(cur, q, q2, out);
        } else if (i == 4) {
            phase_colsum<2>(cur, q);  batch_sync(b);
            phase_fused<2, 1>(cur, q, q2, out);
        } else if (i == 5) {
            phase_colsum<1>(cur, q);  batch_sync(b);
            phase_fused<1, 0>(cur, q, q2, out);
        } else {
            phase_colsum<0>(cur, q);  batch_sync(b);
            phase_fused<0, 0>(cur, q, q2, out);
        }
        batch_sync(b);
        cur ^= 1;
    }

    phase_last(cur, out);
}

extern "C" void kernel_launch(void* const* d_in, const int* in_sizes, int n_in,
                              void* d_out, int out_size) {
    const float* x1 = (const float*)d_in[0];
    const float* x2 = (const float*)d_in[1];
    float* out = (float*)d_out;
    dim3 grid(NN / RPC, BB);   // (16, 8) = 128 CTAs, all co-resident (<=148 SMs)
    k_emd<<<grid, NT, SM_TOTAL>>>(x1, x2, out);
}